// round 15
// baseline (speedup 1.0000x reference)
#include <cuda_runtime.h>
#include <cuda_bf16.h>
#include <cmath>
#include <cstdint>

#define D_MODEL 1024
#define D_FF    4096
#define NEXP    8
#define TOKENS  4096            // B*S = 2*2048
#define NASSIGN (TOKENS * 2)    // top-k = 2

// ---------------- device scratch (no allocations allowed) ----------------
__device__ int   g_cnt[NEXP];
__device__ int   g_off[NEXP + 1];
__device__ int   g_perm[NASSIGN];
__device__ float g_wt[NASSIGN];
__device__ float g_probs[TOKENS * NEXP];
__device__ int   g_argmax[TOKENS];
__device__ int   g_tkidx[TOKENS * 2];
__device__ float g_tkw[TOKENS * 2];
// bf16 hi/lo split buffers
__device__ __align__(16) __nv_bfloat16 g_W1h[(size_t)NEXP * D_MODEL * D_FF];
__device__ __align__(16) __nv_bfloat16 g_W1l[(size_t)NEXP * D_MODEL * D_FF];
__device__ __align__(16) __nv_bfloat16 g_W2h[(size_t)NEXP * D_FF * D_MODEL];
__device__ __align__(16) __nv_bfloat16 g_W2l[(size_t)NEXP * D_FF * D_MODEL];
__device__ __align__(16) __nv_bfloat16 g_xh[(size_t)TOKENS * D_MODEL];
__device__ __align__(16) __nv_bfloat16 g_xl[(size_t)TOKENS * D_MODEL];
__device__ __align__(16) __nv_bfloat16 g_hh[(size_t)NASSIGN * D_FF];
__device__ __align__(16) __nv_bfloat16 g_hl[(size_t)NASSIGN * D_FF];

// ---------------- unified GEMM smem stage layout (64x128 tile, 4 stages) ----
// A: 64 rows, pitch 40 elems (80 B). B: 32 k-rows, pitch 136 elems (272 B).
#define A2L_DIFF 5120
#define B2H_OFF 10240
#define B2L_DIFF 8704
#define STAGE2_BYTES 27648
#define STAGES2 4
#define SMEM2_BYTES (STAGES2 * STAGE2_BYTES) // 110592 -> 2 CTAs/SM (221KB < 228KB)

// ---------------- PTX helpers (baseline PTX only) ----------------
__device__ __forceinline__ uint32_t smem_u32(const void* p) {
    uint32_t a;
    asm("{ .reg .u64 t; cvta.to.shared.u64 t, %1; cvt.u32.u64 %0, t; }"
        : "=r"(a) : "l"(p));
    return a;
}
__device__ __forceinline__ void cpa16(uint32_t d, const void* s) {
    asm volatile("cp.async.cg.shared.global [%0], [%1], 16;" :: "r"(d), "l"(s) : "memory");
}
#define CP_COMMIT() asm volatile("cp.async.commit_group;" ::: "memory")
#define CP_WAIT2()  asm volatile("cp.async.wait_group 2;" ::: "memory")
__device__ __forceinline__ void ldsm4(uint32_t* r, uint32_t addr) {
    asm volatile("ldmatrix.sync.aligned.m8n8.x4.shared.b16 {%0,%1,%2,%3}, [%4];"
        : "=r"(r[0]), "=r"(r[1]), "=r"(r[2]), "=r"(r[3]) : "r"(addr));
}
__device__ __forceinline__ void ldsm4t(uint32_t* r, uint32_t addr) {
    asm volatile("ldmatrix.sync.aligned.m8n8.x4.trans.shared.b16 {%0,%1,%2,%3}, [%4];"
        : "=r"(r[0]), "=r"(r[1]), "=r"(r[2]), "=r"(r[3]) : "r"(addr));
}
__device__ __forceinline__ void mma16816(float* c, const uint32_t* a,
                                         uint32_t b0, uint32_t b1) {
    asm volatile("mma.sync.aligned.m16n8k16.row.col.f32.bf16.bf16.f32 "
        "{%0,%1,%2,%3}, {%4,%5,%6,%7}, {%8,%9}, {%0,%1,%2,%3};"
        : "+f"(c[0]), "+f"(c[1]), "+f"(c[2]), "+f"(c[3])
        : "r"(a[0]), "r"(a[1]), "r"(a[2]), "r"(a[3]), "r"(b0), "r"(b1));
}
__device__ __forceinline__ float gelu_exact(float v) {
    return 0.5f * v * (1.0f + erff(v * 0.70710678118654752f));
}
__device__ __forceinline__ uint32_t pack_bf2(__nv_bfloat16 a, __nv_bfloat16 b) {
    return (uint32_t)__bfloat16_as_ushort(a) | ((uint32_t)__bfloat16_as_ushort(b) << 16);
}

// ---------------- unified compute chunk (warp tile 32x32, 2m x 4n grid) -----
__device__ __forceinline__ void compute_chunk2(uint32_t sbS, int wm, int wn, int lid,
                                               float (&acc)[2][4][4]) {
    const int lr = lid & 15;
    const int lc = (lid >> 4) * 8;
    #pragma unroll
    for (int ks = 0; ks < 2; ks++) {
        uint32_t ah[2][4], al[2][4];
        #pragma unroll
        for (int mi = 0; mi < 2; mi++) {
            uint32_t ra = sbS +
                (uint32_t)(((wm * 32 + mi * 16 + lr) * 40 + ks * 16 + lc) * 2);
            ldsm4(ah[mi], ra);
            ldsm4(al[mi], ra + A2L_DIFF);
        }
        #pragma unroll
        for (int nq = 0; nq < 2; nq++) {
            uint32_t bh[4], bl[4];
            uint32_t rb = sbS + B2H_OFF +
                (uint32_t)(((ks * 16 + lr) * 136 + wn * 32 + nq * 16 + lc) * 2);
            ldsm4t(bh, rb);
            ldsm4t(bl, rb + B2L_DIFF);
            float* a00 = acc[0][nq * 2];
            float* a01 = acc[0][nq * 2 + 1];
            float* a10 = acc[1][nq * 2];
            float* a11 = acc[1][nq * 2 + 1];
            mma16816(a00, ah[0], bh[0], bh[1]);
            mma16816(a10, ah[1], bh[0], bh[1]);
            mma16816(a01, ah[0], bh[2], bh[3]);
            mma16816(a11, ah[1], bh[2], bh[3]);
            mma16816(a00, ah[0], bl[0], bl[1]);
            mma16816(a10, ah[1], bl[0], bl[1]);
            mma16816(a01, ah[0], bl[2], bl[3]);
            mma16816(a11, ah[1], bl[2], bl[3]);
            mma16816(a00, al[0], bh[0], bh[1]);
            mma16816(a10, al[1], bh[0], bh[1]);
            mma16816(a01, al[0], bh[2], bh[3]);
            mma16816(a11, al[1], bh[2], bh[3]);
        }
    }
}

// ---------------- fp32 -> bf16 hi/lo pre-split (16B stores, ILP 4) ----------
__global__ void conv_split(const float* __restrict__ src,
                           __nv_bfloat16* __restrict__ hi,
                           __nv_bfloat16* __restrict__ lo) {
    const size_t base8 = (size_t)blockIdx.x * (blockDim.x * 4) + threadIdx.x;
    #pragma unroll
    for (int k = 0; k < 4; k++) {
        const size_t g = base8 + (size_t)k * blockDim.x;
        float4 v0 = ((const float4*)src)[g * 2];
        float4 v1 = ((const float4*)src)[g * 2 + 1];
        __nv_bfloat16 h0 = __float2bfloat16_rn(v0.x);
        __nv_bfloat16 h1 = __float2bfloat16_rn(v0.y);
        __nv_bfloat16 h2 = __float2bfloat16_rn(v0.z);
        __nv_bfloat16 h3 = __float2bfloat16_rn(v0.w);
        __nv_bfloat16 h4 = __float2bfloat16_rn(v1.x);
        __nv_bfloat16 h5 = __float2bfloat16_rn(v1.y);
        __nv_bfloat16 h6 = __float2bfloat16_rn(v1.z);
        __nv_bfloat16 h7 = __float2bfloat16_rn(v1.w);
        uint4 H, L;
        H.x = pack_bf2(h0, h1);
        H.y = pack_bf2(h2, h3);
        H.z = pack_bf2(h4, h5);
        H.w = pack_bf2(h6, h7);
        L.x = pack_bf2(__float2bfloat16_rn(v0.x - __bfloat162float(h0)),
                       __float2bfloat16_rn(v0.y - __bfloat162float(h1)));
        L.y = pack_bf2(__float2bfloat16_rn(v0.z - __bfloat162float(h2)),
                       __float2bfloat16_rn(v0.w - __bfloat162float(h3)));
        L.z = pack_bf2(__float2bfloat16_rn(v1.x - __bfloat162float(h4)),
                       __float2bfloat16_rn(v1.y - __bfloat162float(h5)));
        L.w = pack_bf2(__float2bfloat16_rn(v1.z - __bfloat162float(h6)),
                       __float2bfloat16_rn(v1.w - __bfloat162float(h7)));
        ((uint4*)hi)[g] = H;
        ((uint4*)lo)[g] = L;
    }
}

// ---------------- router (also emits the x bf16 hi/lo split) ----------------
__global__ void router_kernel(const float* __restrict__ x,
                              const float* __restrict__ Wr,
                              const float* __restrict__ br,
                              __nv_bfloat16* __restrict__ xh,
                              __nv_bfloat16* __restrict__ xl) {
    const int t = blockIdx.x;
    const float* xr = x + (size_t)t * D_MODEL;
    float acc[NEXP];
    #pragma unroll
    for (int e = 0; e < NEXP; e++) acc[e] = 0.f;
    for (int d = threadIdx.x; d < D_MODEL; d += 128) {
        float xv = xr[d];
        __nv_bfloat16 h = __float2bfloat16_rn(xv);
        xh[(size_t)t * D_MODEL + d] = h;
        xl[(size_t)t * D_MODEL + d] = __float2bfloat16_rn(xv - __bfloat162float(h));
        const float* w = Wr + d * NEXP;
        #pragma unroll
        for (int e = 0; e < NEXP; e++) acc[e] = fmaf(xv, w[e], acc[e]);
    }
    __shared__ float red[NEXP][128];
    #pragma unroll
    for (int e = 0; e < NEXP; e++) red[e][threadIdx.x] = acc[e];
    __syncthreads();
    for (int s = 64; s > 0; s >>= 1) {
        if (threadIdx.x < s) {
            #pragma unroll
            for (int e = 0; e < NEXP; e++)
                red[e][threadIdx.x] += red[e][threadIdx.x + s];
        }
        __syncthreads();
    }
    if (threadIdx.x == 0) {
        float lg[NEXP], p[NEXP];
        float mx = -1e30f;
        #pragma unroll
        for (int e = 0; e < NEXP; e++) { lg[e] = red[e][0] + br[e]; mx = fmaxf(mx, lg[e]); }
        float s = 0.f;
        #pragma unroll
        for (int e = 0; e < NEXP; e++) { p[e] = expf(lg[e] - mx); s += p[e]; }
        float inv = 1.f / s;
        #pragma unroll
        for (int e = 0; e < NEXP; e++) { p[e] *= inv; g_probs[t * NEXP + e] = p[e]; }
        int i1 = 0;
        #pragma unroll
        for (int e = 1; e < NEXP; e++) if (p[e] > p[i1]) i1 = e;
        int i2 = (i1 == 0) ? 1 : 0;
        #pragma unroll
        for (int e = 0; e < NEXP; e++) if (e != i1 && p[e] > p[i2]) i2 = e;
        float v1 = p[i1], v2 = p[i2];
        float sum = fmaxf(v1 + v2, 1e-9f);
        g_tkidx[2 * t] = i1;  g_tkidx[2 * t + 1] = i2;
        g_tkw[2 * t] = v1 / sum;  g_tkw[2 * t + 1] = v2 / sum;
        g_argmax[t] = i1;
    }
}

// ---------------- deterministic per-expert compaction (1024 thr, 128 chunks)
#define NCH 128
__global__ void build_lists_kernel() {
    __shared__ int scnt[NCH][NEXP];
    __shared__ int choff[NCH][NEXP];
    __shared__ int eoff[NEXP];
    const int tid = threadIdx.x;
    const int e = tid & 7, ch = tid >> 3;
    const int t0 = ch * (TOKENS / NCH);
    int c = 0;
    for (int t = t0; t < t0 + TOKENS / NCH; t++) {
        if (g_tkidx[2 * t]     == e) c++;
        if (g_tkidx[2 * t + 1] == e) c++;
    }
    scnt[ch][e] = c;
    __syncthreads();
    if (tid < NEXP) {
        int s = 0;
        for (int j = 0; j < NCH; j++) { choff[j][tid] = s; s += scnt[j][tid]; }
        g_cnt[tid] = s;
    }
    __syncthreads();
    if (tid == 0) {
        int s = 0;
        for (int j = 0; j < NEXP; j++) { eoff[j] = s; g_off[j] = s; s += g_cnt[j]; }
        g_off[NEXP] = s;
    }
    __syncthreads();
    int pos = eoff[e] + choff[ch][e];
    for (int t = t0; t < t0 + TOKENS / NCH; t++) {
        #pragma unroll
        for (int k = 0; k < 2; k++)
            if (g_tkidx[2 * t + k] == e) {
                g_perm[pos] = t;
                g_wt[pos]   = g_tkw[2 * t + k];
                pos++;
            }
    }
}

// ---------------- aux loss ----------------
__global__ void aux_kernel(float* __restrict__ out, int out_size) {
    __shared__ float sp[NEXP][256];
    __shared__ int   sc[NEXP][256];
    const int tid = threadIdx.x;
    float p[NEXP]; int cc[NEXP];
    #pragma unroll
    for (int e = 0; e < NEXP; e++) { p[e] = 0.f; cc[e] = 0; }
    for (int t = tid; t < TOKENS; t += 256) {
        #pragma unroll
        for (int e = 0; e < NEXP; e++) p[e] += g_probs[t * NEXP + e];
        cc[g_argmax[t]]++;
    }
    #pragma unroll
    for (int e = 0; e < NEXP; e++) { sp[e][tid] = p[e]; sc[e][tid] = cc[e]; }
    __syncthreads();
    for (int s = 128; s > 0; s >>= 1) {
        if (tid < s) {
            #pragma unroll
            for (int e = 0; e < NEXP; e++) {
                sp[e][tid] += sp[e][tid + s];
                sc[e][tid] += sc[e][tid + s];
            }
        }
        __syncthreads();
    }
    if (tid == 0 && out_size > TOKENS * D_MODEL) {
        float aux = 0.f;
        #pragma unroll
        for (int e = 0; e < NEXP; e++)
            aux += ((float)sc[e][0] / (float)TOKENS) * (sp[e][0] / (float)TOKENS);
        out[out_size - 1] = (float)NEXP * aux;
    }
}

// ---------------- GEMM1 (64x128 tile): h = gelu(X_e @ W1[e] + b1) -----------
__global__ __launch_bounds__(256, 2)
void gemm1_mma(const __nv_bfloat16* __restrict__ xh,
               const __nv_bfloat16* __restrict__ xl,
               const __nv_bfloat16* __restrict__ W1h,
               const __nv_bfloat16* __restrict__ W1l,
               const float* __restrict__ b1,
               __nv_bfloat16* __restrict__ hh,
               __nv_bfloat16* __restrict__ hl) {
    const int e   = blockIdx.z;
    const int cnt = g_cnt[e];
    const int m0  = blockIdx.y * 64;
    if (m0 >= cnt) return;
    const int n0  = blockIdx.x * 128;
    const int off = g_off[e];

    extern __shared__ __align__(128) char smem[];
    const uint32_t sb = smem_u32(smem);
    const int tid = threadIdx.x;
    const int lid = tid & 31;
    const int wid = tid >> 5;
    const int wm = wid >> 2, wn = wid & 3;   // 2m x 4n warp grid

    // A producer: 64 rows (token-gathered), h/l
    const int rA = tid >> 2;             // 0..63
    const int sA = (tid & 3) * 16;
    const int tokA = (m0 + rA < cnt) ? g_perm[off + m0 + rA] : g_perm[off];
    const __nv_bfloat16* a_h = xh + (size_t)tokA * D_MODEL + (sA >> 1);
    const __nv_bfloat16* a_l = xl + (size_t)tokA * D_MODEL + (sA >> 1);
    const uint32_t oA = (uint32_t)(rA * 80 + sA);

    // B producer: 32 k-rows x 128 n (stride D_FF)
    const int rB0 = tid >> 4;
    const int sB  = (tid & 15) * 16;
    const __nv_bfloat16* b_h = W1h + (size_t)e * D_MODEL * D_FF + (size_t)rB0 * D_FF + n0 + (sB >> 1);
    const __nv_bfloat16* b_l = W1l + (size_t)e * D_MODEL * D_FF + (size_t)rB0 * D_FF + n0 + (sB >> 1);
    const uint32_t oB0 = (uint32_t)(B2H_OFF + rB0 * 272 + sB);
    const uint32_t oB1 = (uint32_t)(B2H_OFF + (rB0 + 16) * 272 + sB);

    float acc[2][4][4];
    #pragma unroll
    for (int i = 0; i < 2; i++)
        #pragma unroll
        for (int j = 0; j < 4; j++)
            #pragma unroll
            for (int k = 0; k < 4; k++) acc[i][j][k] = 0.f;

    auto issue = [&](int c) {
        uint32_t st = sb + (uint32_t)((c & (STAGES2 - 1)) * STAGE2_BYTES);
        const int k0 = c * 32;
        cpa16(st + oA, a_h + k0);
        cpa16(st + oA + A2L_DIFF, a_l + k0);
        const size_t bk = (size_t)k0 * D_FF;
        cpa16(st + oB0, b_h + bk);
        cpa16(st + oB1, b_h + bk + (size_t)16 * D_FF);
        cpa16(st + oB0 + B2L_DIFF, b_l + bk);
        cpa16(st + oB1 + B2L_DIFF, b_l + bk + (size_t)16 * D_FF);
        CP_COMMIT();
    };

    const int NC = D_MODEL / 32;   // 32
    issue(0); issue(1); issue(2);
    for (int c = 0; c < NC; c++) {
        CP_WAIT2();
        __syncthreads();
        if (c + 3 < NC) issue(c + 3);
        compute_chunk2(sb + (uint32_t)((c & (STAGES2 - 1)) * STAGE2_BYTES), wm, wn, lid, acc);
    }

    // epilogue: bias + exact gelu -> bf16 hi/lo stores
    const int lgrp  = lid >> 2;
    const int lquad = (lid & 3) * 2;
    #pragma unroll
    for (int mi = 0; mi < 2; mi++) {
        const int r0 = m0 + wm * 32 + mi * 16 + lgrp;
        const int r1 = r0 + 8;
        #pragma unroll
        for (int n4 = 0; n4 < 4; n4++) {
            const int colg = n0 + wn * 32 + n4 * 8 + lquad;
            float2 bb = *(const float2*)(b1 + e * D_FF + colg);
            const float* a4 = acc[mi][n4];
            if (r0 < cnt) {
                float v0 = gelu_exact(a4[0] + bb.x);
                float v1 = gelu_exact(a4[1] + bb.y);
                __nv_bfloat16 h0 = __float2bfloat16_rn(v0);
                __nv_bfloat16 h1 = __float2bfloat16_rn(v1);
                size_t base = (size_t)(off + r0) * D_FF + colg;
                *(uint32_t*)(hh + base) = pack_bf2(h0, h1);
                *(uint32_t*)(hl + base) = pack_bf2(
                    __float2bfloat16_rn(v0 - __bfloat162float(h0)),
                    __float2bfloat16_rn(v1 - __bfloat162float(h1)));
            }
            if (r1 < cnt) {
                float v0 = gelu_exact(a4[2] + bb.x);
                float v1 = gelu_exact(a4[3] + bb.y);
                __nv_bfloat16 h0 = __float2bfloat16_rn(v0);
                __nv_bfloat16 h1 = __float2bfloat16_rn(v1);
                size_t base = (size_t)(off + r1) * D_FF + colg;
                *(uint32_t*)(hh + base) = pack_bf2(h0, h1);
                *(uint32_t*)(hl + base) = pack_bf2(
                    __float2bfloat16_rn(v0 - __bfloat162float(h0)),
                    __float2bfloat16_rn(v1 - __bfloat162float(h1)));
            }
        }
    }
}

// ---------------- GEMM2 (64x128 tile): out += w*(H_e @ W2[e] + b2) ----------
__global__ __launch_bounds__(256, 2)
void gemm2_mma(const __nv_bfloat16* __restrict__ hh,
               const __nv_bfloat16* __restrict__ hl,
               const __nv_bfloat16* __restrict__ W2h,
               const __nv_bfloat16* __restrict__ W2l,
               const float* __restrict__ b2,
               float* __restrict__ out) {
    const int e   = blockIdx.z;
    const int cnt = g_cnt[e];
    const int m0  = blockIdx.y * 64;
    if (m0 >= cnt) return;
    const int n0  = blockIdx.x * 128;
    const int off = g_off[e];

    extern __shared__ __align__(128) char smem[];
    const uint32_t sb = smem_u32(smem);
    const int tid = threadIdx.x;
    const int lid = tid & 31;
    const int wid = tid >> 5;
    const int wm = wid >> 2, wn = wid & 3;

    const int rA = tid >> 2;
    const int sA = (tid & 3) * 16;
    const int rowA = (m0 + rA < cnt) ? (off + m0 + rA) : off;
    const __nv_bfloat16* a_h = hh + (size_t)rowA * D_FF + (sA >> 1);
    const __nv_bfloat16* a_l = hl + (size_t)rowA * D_FF + (sA >> 1);
    const uint32_t oA = (uint32_t)(rA * 80 + sA);

    const int rB0 = tid >> 4;
    const int sB  = (tid & 15) * 16;
    const __nv_bfloat16* b_h = W2h + (size_t)e * D_FF * D_MODEL + (size_t)rB0 * D_MODEL + n0 + (sB >> 1);
    const __nv_bfloat16* b_l = W2l + (size_t)e * D_FF * D_MODEL + (size_t)rB0 * D_MODEL + n0 + (sB >> 1);
    const uint32_t oB0 = (uint32_t)(B2H_OFF + rB0 * 272 + sB);
    const uint32_t oB1 = (uint32_t)(B2H_OFF + (rB0 + 16) * 272 + sB);

    float acc[2][4][4];
    #pragma unroll
    for (int i = 0; i < 2; i++)
        #pragma unroll
        for (int j = 0; j < 4; j++)
            #pragma unroll
            for (int k = 0; k < 4; k++) acc[i][j][k] = 0.f;

    auto issue = [&](int c) {
        uint32_t st = sb + (uint32_t)((c & (STAGES2 - 1)) * STAGE2_BYTES);
        const int k0 = c * 32;
        cpa16(st + oA, a_h + k0);
        cpa16(st + oA + A2L_DIFF, a_l + k0);
        const size_t bk = (size_t)k0 * D_MODEL;
        cpa16(st + oB0, b_h + bk);
        cpa16(st + oB1, b_h + bk + (size_t)16 * D_MODEL);
        cpa16(st + oB0 + B2L_DIFF, b_l + bk);
        cpa16(st + oB1 + B2L_DIFF, b_l + bk + (size_t)16 * D_MODEL);
        CP_COMMIT();
    };

    const int NC = D_FF / 32;   // 128
    issue(0); issue(1); issue(2);
    for (int c = 0; c < NC; c++) {
        CP_WAIT2();
        __syncthreads();
        if (c + 3 < NC) issue(c + 3);
        compute_chunk2(sb + (uint32_t)((c & (STAGES2 - 1)) * STAGE2_BYTES), wm, wn, lid, acc);
    }

    // epilogue: bias, gate-weight scale, vector atomic accumulate
    const int lgrp  = lid >> 2;
    const int lquad = (lid & 3) * 2;
    #pragma unroll
    for (int mi = 0; mi < 2; mi++) {
        const int r0 = m0 + wm * 32 + mi * 16 + lgrp;
        const int r1 = r0 + 8;
        const bool v0 = r0 < cnt, v1 = r1 < cnt;
        const int  s0 = v0 ? (off + r0) : off;
        const int  s1 = v1 ? (off + r1) : off;
        const int  t0 = g_perm[s0], t1 = g_perm[s1];
        const float w0 = v0 ? g_wt[s0] : 0.f;
        const float w1 = v1 ? g_wt[s1] : 0.f;
        #pragma unroll
        for (int n4 = 0; n4 < 4; n4++) {
            const int colg = n0 + wn * 32 + n4 * 8 + lquad;
            float2 bb = *(const float2*)(b2 + e * D_MODEL + colg);
            const float* a4 = acc[mi][n4];
            if (v0) {
                float2 v = make_float2(w0 * (a4[0] + bb.x), w0 * (a4[1] + bb.y));
                atomicAdd((float2*)(out + (size_t)t0 * D_MODEL + colg), v);
            }
            if (v1) {
                float2 v = make_float2(w1 * (a4[2] + bb.x), w1 * (a4[3] + bb.y));
                atomicAdd((float2*)(out + (size_t)t1 * D_MODEL + colg), v);
            }
        }
    }
}

// ---------------- launch: conv(W) || routing(+x-split), FULL join, GEMMs ----
extern "C" void kernel_launch(void* const* d_in, const int* in_sizes, int n_in,
                              void* d_out, int out_size) {
    const float* x  = (const float*)d_in[0];
    const float* Wr = (const float*)d_in[1];
    const float* br = (const float*)d_in[2];
    const float* W1 = (const float*)d_in[3];
    const float* b1 = (const float*)d_in[4];
    const float* W2 = (const float*)d_in[5];
    const float* b2 = (const float*)d_in[6];
    float* out = (float*)d_out;

    void *pW1h, *pW1l, *pW2h, *pW2l, *pxh, *pxl, *phh, *phl;
    cudaGetSymbolAddress(&pW1h, g_W1h);
    cudaGetSymbolAddress(&pW1l, g_W1l);
    cudaGetSymbolAddress(&pW2h, g_W2h);
    cudaGetSymbolAddress(&pW2l, g_W2l);
    cudaGetSymbolAddress(&pxh,  g_xh);
    cudaGetSymbolAddress(&pxl,  g_xl);
    cudaGetSymbolAddress(&phh,  g_hh);
    cudaGetSymbolAddress(&phl,  g_hl);

    cudaFuncSetAttribute(gemm1_mma, cudaFuncAttributeMaxDynamicSharedMemorySize, SMEM2_BYTES);
    cudaFuncSetAttribute(gemm2_mma, cudaFuncAttributeMaxDynamicSharedMemorySize, SMEM2_BYTES);

    cudaStream_t s1;
    cudaEvent_t ev0, ev1;
    cudaStreamCreateWithFlags(&s1, cudaStreamNonBlocking);
    cudaEventCreateWithFlags(&ev0, cudaEventDisableTiming);
    cudaEventCreateWithFlags(&ev1, cudaEventDisableTiming);

    const int nW8 = NEXP * D_MODEL * D_FF / 8;   // 4194304 8-float groups

    // fork
    cudaEventRecord(ev0, 0);
    cudaStreamWaitEvent(s1, ev0, 0);

    // side stream: weight conv passes
    conv_split<<<nW8 / 1024, 256, 0, s1>>>(W1, (__nv_bfloat16*)pW1h, (__nv_bfloat16*)pW1l);
    conv_split<<<nW8 / 1024, 256, 0, s1>>>(W2, (__nv_bfloat16*)pW2h, (__nv_bfloat16*)pW2l);
    cudaEventRecord(ev1, s1);

    // main stream: routing chain (router also writes the x split)
    cudaMemsetAsync(out, 0, (size_t)TOKENS * D_MODEL * sizeof(float), 0);
    router_kernel<<<TOKENS, 128>>>(x, Wr, br, (__nv_bfloat16*)pxh, (__nv_bfloat16*)pxl);
    build_lists_kernel<<<1, 1024>>>();
    aux_kernel<<<1, 256>>>(out, out_size);

    // FULL join: GEMMs run with the GPU to themselves
    cudaStreamWaitEvent(0, ev1, 0);
    gemm1_mma<<<dim3(D_FF / 128, TOKENS / 64, NEXP), 256, SMEM2_BYTES>>>(
        (const __nv_bfloat16*)pxh, (const __nv_bfloat16*)pxl,
        (const __nv_bfloat16*)pW1h, (const __nv_bfloat16*)pW1l, b1,
        (__nv_bfloat16*)phh, (__nv_bfloat16*)phl);
    gemm2_mma<<<dim3(D_MODEL / 128, TOKENS / 64, NEXP), 256, SMEM2_BYTES>>>(
        (const __nv_bfloat16*)phh, (const __nv_bfloat16*)phl,
        (const __nv_bfloat16*)pW2h, (const __nv_bfloat16*)pW2l, b2, out);
}

// round 16
// speedup vs baseline: 1.0090x; 1.0090x over previous
#include <cuda_runtime.h>
#include <cuda_bf16.h>
#include <cmath>
#include <cstdint>

#define D_MODEL 1024
#define D_FF    4096
#define NEXP    8
#define TOKENS  4096            // B*S = 2*2048
#define NASSIGN (TOKENS * 2)    // top-k = 2

// ---------------- device scratch (no allocations allowed) ----------------
__device__ int   g_cnt[NEXP];
__device__ int   g_off[NEXP + 1];
__device__ int   g_perm[NASSIGN];
__device__ float g_wt[NASSIGN];
__device__ float g_probs[TOKENS * NEXP];
__device__ int   g_argmax[TOKENS];
__device__ int   g_tkidx[TOKENS * 2];
__device__ float g_tkw[TOKENS * 2];
// bf16 hi/lo split buffers
__device__ __align__(16) __nv_bfloat16 g_W1h[(size_t)NEXP * D_MODEL * D_FF];
__device__ __align__(16) __nv_bfloat16 g_W1l[(size_t)NEXP * D_MODEL * D_FF];
__device__ __align__(16) __nv_bfloat16 g_W2h[(size_t)NEXP * D_FF * D_MODEL];
__device__ __align__(16) __nv_bfloat16 g_W2l[(size_t)NEXP * D_FF * D_MODEL];
__device__ __align__(16) __nv_bfloat16 g_xh[(size_t)TOKENS * D_MODEL];
__device__ __align__(16) __nv_bfloat16 g_xl[(size_t)TOKENS * D_MODEL];
__device__ __align__(16) __nv_bfloat16 g_hh[(size_t)NASSIGN * D_FF];
__device__ __align__(16) __nv_bfloat16 g_hl[(size_t)NASSIGN * D_FF];

// ---------------- GEMM1 smem stage layout (128x128 tile) ----------------
#define AH_OFF 0
#define AL_OFF 10240
#define BH_OFF 20480
#define BL_OFF 29184
#define STAGE_BYTES 37888
#define STAGES 3
#define SMEM_BYTES (STAGES * STAGE_BYTES)   // 113664 -> 2 CTAs/SM

// ---------------- GEMM2 smem stage layout (64x128 tile, 4 stages) --------
#define A2L_DIFF 5120
#define B2H_OFF 10240
#define B2L_DIFF 8704
#define STAGE2_BYTES 27648
#define STAGES2 4
#define SMEM2_BYTES (STAGES2 * STAGE2_BYTES) // 110592 -> 2 CTAs/SM (221KB < 228KB)

// ---------------- PTX helpers (baseline PTX only) ----------------
__device__ __forceinline__ uint32_t smem_u32(const void* p) {
    uint32_t a;
    asm("{ .reg .u64 t; cvta.to.shared.u64 t, %1; cvt.u32.u64 %0, t; }"
        : "=r"(a) : "l"(p));
    return a;
}
__device__ __forceinline__ void cpa16(uint32_t d, const void* s) {
    asm volatile("cp.async.cg.shared.global [%0], [%1], 16;" :: "r"(d), "l"(s) : "memory");
}
#define CP_COMMIT() asm volatile("cp.async.commit_group;" ::: "memory")
#define CP_WAIT1()  asm volatile("cp.async.wait_group 1;" ::: "memory")
#define CP_WAIT2()  asm volatile("cp.async.wait_group 2;" ::: "memory")
__device__ __forceinline__ void ldsm4(uint32_t* r, uint32_t addr) {
    asm volatile("ldmatrix.sync.aligned.m8n8.x4.shared.b16 {%0,%1,%2,%3}, [%4];"
        : "=r"(r[0]), "=r"(r[1]), "=r"(r[2]), "=r"(r[3]) : "r"(addr));
}
__device__ __forceinline__ void ldsm4t(uint32_t* r, uint32_t addr) {
    asm volatile("ldmatrix.sync.aligned.m8n8.x4.trans.shared.b16 {%0,%1,%2,%3}, [%4];"
        : "=r"(r[0]), "=r"(r[1]), "=r"(r[2]), "=r"(r[3]) : "r"(addr));
}
__device__ __forceinline__ void mma16816(float* c, const uint32_t* a,
                                         uint32_t b0, uint32_t b1) {
    asm volatile("mma.sync.aligned.m16n8k16.row.col.f32.bf16.bf16.f32 "
        "{%0,%1,%2,%3}, {%4,%5,%6,%7}, {%8,%9}, {%0,%1,%2,%3};"
        : "+f"(c[0]), "+f"(c[1]), "+f"(c[2]), "+f"(c[3])
        : "r"(a[0]), "r"(a[1]), "r"(a[2]), "r"(a[3]), "r"(b0), "r"(b1));
}
__device__ __forceinline__ float gelu_exact(float v) {
    return 0.5f * v * (1.0f + erff(v * 0.70710678118654752f));
}
__device__ __forceinline__ uint32_t pack_bf2(__nv_bfloat16 a, __nv_bfloat16 b) {
    return (uint32_t)__bfloat16_as_ushort(a) | ((uint32_t)__bfloat16_as_ushort(b) << 16);
}

// ---------------- GEMM1 compute chunk (warp tile 32x64) ----------------
__device__ __forceinline__ void compute_chunk(uint32_t sbS, int wm, int wn, int lid,
                                              float (&acc)[2][8][4]) {
    const int lr = lid & 15;
    const int lc = (lid >> 4) * 8;
    #pragma unroll
    for (int ks = 0; ks < 2; ks++) {
        uint32_t ah[2][4], al[2][4];
        #pragma unroll
        for (int mi = 0; mi < 2; mi++) {
            uint32_t ra = sbS + AH_OFF +
                (uint32_t)(((wm * 32 + mi * 16 + lr) * 40 + ks * 16 + lc) * 2);
            ldsm4(ah[mi], ra);
            ldsm4(al[mi], ra + (AL_OFF - AH_OFF));
        }
        #pragma unroll
        for (int nq = 0; nq < 4; nq++) {
            uint32_t bh[4], bl[4];
            uint32_t rb = sbS + BH_OFF +
                (uint32_t)(((ks * 16 + lr) * 136 + wn * 64 + nq * 16 + lc) * 2);
            ldsm4t(bh, rb);
            ldsm4t(bl, rb + (BL_OFF - BH_OFF));
            float* a00 = acc[0][nq * 2];
            float* a01 = acc[0][nq * 2 + 1];
            float* a10 = acc[1][nq * 2];
            float* a11 = acc[1][nq * 2 + 1];
            mma16816(a00, ah[0], bh[0], bh[1]);
            mma16816(a10, ah[1], bh[0], bh[1]);
            mma16816(a01, ah[0], bh[2], bh[3]);
            mma16816(a11, ah[1], bh[2], bh[3]);
            mma16816(a00, ah[0], bl[0], bl[1]);
            mma16816(a10, ah[1], bl[0], bl[1]);
            mma16816(a01, ah[0], bl[2], bl[3]);
            mma16816(a11, ah[1], bl[2], bl[3]);
            mma16816(a00, al[0], bh[0], bh[1]);
            mma16816(a10, al[1], bh[0], bh[1]);
            mma16816(a01, al[0], bh[2], bh[3]);
            mma16816(a11, al[1], bh[2], bh[3]);
        }
    }
}

// ---------------- GEMM2 compute chunk (warp tile 32x32) ----------------
__device__ __forceinline__ void compute_chunk2(uint32_t sbS, int wm, int wn, int lid,
                                               float (&acc)[2][4][4]) {
    const int lr = lid & 15;
    const int lc = (lid >> 4) * 8;
    #pragma unroll
    for (int ks = 0; ks < 2; ks++) {
        uint32_t ah[2][4], al[2][4];
        #pragma unroll
        for (int mi = 0; mi < 2; mi++) {
            uint32_t ra = sbS +
                (uint32_t)(((wm * 32 + mi * 16 + lr) * 40 + ks * 16 + lc) * 2);
            ldsm4(ah[mi], ra);
            ldsm4(al[mi], ra + A2L_DIFF);
        }
        #pragma unroll
        for (int nq = 0; nq < 2; nq++) {
            uint32_t bh[4], bl[4];
            uint32_t rb = sbS + B2H_OFF +
                (uint32_t)(((ks * 16 + lr) * 136 + wn * 32 + nq * 16 + lc) * 2);
            ldsm4t(bh, rb);
            ldsm4t(bl, rb + B2L_DIFF);
            float* a00 = acc[0][nq * 2];
            float* a01 = acc[0][nq * 2 + 1];
            float* a10 = acc[1][nq * 2];
            float* a11 = acc[1][nq * 2 + 1];
            mma16816(a00, ah[0], bh[0], bh[1]);
            mma16816(a10, ah[1], bh[0], bh[1]);
            mma16816(a01, ah[0], bh[2], bh[3]);
            mma16816(a11, ah[1], bh[2], bh[3]);
            mma16816(a00, ah[0], bl[0], bl[1]);
            mma16816(a10, ah[1], bl[0], bl[1]);
            mma16816(a01, ah[0], bl[2], bl[3]);
            mma16816(a11, ah[1], bl[2], bl[3]);
            mma16816(a00, al[0], bh[0], bh[1]);
            mma16816(a10, al[1], bh[0], bh[1]);
            mma16816(a01, al[0], bh[2], bh[3]);
            mma16816(a11, al[1], bh[2], bh[3]);
        }
    }
}

// ---------------- fp32 -> bf16 hi/lo pre-split (16B stores, ILP 4) ----------
__global__ void conv_split(const float* __restrict__ src,
                           __nv_bfloat16* __restrict__ hi,
                           __nv_bfloat16* __restrict__ lo) {
    const size_t base8 = (size_t)blockIdx.x * (blockDim.x * 4) + threadIdx.x;
    #pragma unroll
    for (int k = 0; k < 4; k++) {
        const size_t g = base8 + (size_t)k * blockDim.x;
        float4 v0 = ((const float4*)src)[g * 2];
        float4 v1 = ((const float4*)src)[g * 2 + 1];
        __nv_bfloat16 h0 = __float2bfloat16_rn(v0.x);
        __nv_bfloat16 h1 = __float2bfloat16_rn(v0.y);
        __nv_bfloat16 h2 = __float2bfloat16_rn(v0.z);
        __nv_bfloat16 h3 = __float2bfloat16_rn(v0.w);
        __nv_bfloat16 h4 = __float2bfloat16_rn(v1.x);
        __nv_bfloat16 h5 = __float2bfloat16_rn(v1.y);
        __nv_bfloat16 h6 = __float2bfloat16_rn(v1.z);
        __nv_bfloat16 h7 = __float2bfloat16_rn(v1.w);
        uint4 H, L;
        H.x = pack_bf2(h0, h1);
        H.y = pack_bf2(h2, h3);
        H.z = pack_bf2(h4, h5);
        H.w = pack_bf2(h6, h7);
        L.x = pack_bf2(__float2bfloat16_rn(v0.x - __bfloat162float(h0)),
                       __float2bfloat16_rn(v0.y - __bfloat162float(h1)));
        L.y = pack_bf2(__float2bfloat16_rn(v0.z - __bfloat162float(h2)),
                       __float2bfloat16_rn(v0.w - __bfloat162float(h3)));
        L.z = pack_bf2(__float2bfloat16_rn(v1.x - __bfloat162float(h4)),
                       __float2bfloat16_rn(v1.y - __bfloat162float(h5)));
        L.w = pack_bf2(__float2bfloat16_rn(v1.z - __bfloat162float(h6)),
                       __float2bfloat16_rn(v1.w - __bfloat162float(h7)));
        ((uint4*)hi)[g] = H;
        ((uint4*)lo)[g] = L;
    }
}

// ---------------- router (also emits the x bf16 hi/lo split) ----------------
__global__ void router_kernel(const float* __restrict__ x,
                              const float* __restrict__ Wr,
                              const float* __restrict__ br,
                              __nv_bfloat16* __restrict__ xh,
                              __nv_bfloat16* __restrict__ xl) {
    const int t = blockIdx.x;
    const float* xr = x + (size_t)t * D_MODEL;
    float acc[NEXP];
    #pragma unroll
    for (int e = 0; e < NEXP; e++) acc[e] = 0.f;
    for (int d = threadIdx.x; d < D_MODEL; d += 128) {
        float xv = xr[d];
        __nv_bfloat16 h = __float2bfloat16_rn(xv);
        xh[(size_t)t * D_MODEL + d] = h;
        xl[(size_t)t * D_MODEL + d] = __float2bfloat16_rn(xv - __bfloat162float(h));
        const float* w = Wr + d * NEXP;
        #pragma unroll
        for (int e = 0; e < NEXP; e++) acc[e] = fmaf(xv, w[e], acc[e]);
    }
    __shared__ float red[NEXP][128];
    #pragma unroll
    for (int e = 0; e < NEXP; e++) red[e][threadIdx.x] = acc[e];
    __syncthreads();
    for (int s = 64; s > 0; s >>= 1) {
        if (threadIdx.x < s) {
            #pragma unroll
            for (int e = 0; e < NEXP; e++)
                red[e][threadIdx.x] += red[e][threadIdx.x + s];
        }
        __syncthreads();
    }
    if (threadIdx.x == 0) {
        float lg[NEXP], p[NEXP];
        float mx = -1e30f;
        #pragma unroll
        for (int e = 0; e < NEXP; e++) { lg[e] = red[e][0] + br[e]; mx = fmaxf(mx, lg[e]); }
        float s = 0.f;
        #pragma unroll
        for (int e = 0; e < NEXP; e++) { p[e] = expf(lg[e] - mx); s += p[e]; }
        float inv = 1.f / s;
        #pragma unroll
        for (int e = 0; e < NEXP; e++) { p[e] *= inv; g_probs[t * NEXP + e] = p[e]; }
        int i1 = 0;
        #pragma unroll
        for (int e = 1; e < NEXP; e++) if (p[e] > p[i1]) i1 = e;
        int i2 = (i1 == 0) ? 1 : 0;
        #pragma unroll
        for (int e = 0; e < NEXP; e++) if (e != i1 && p[e] > p[i2]) i2 = e;
        float v1 = p[i1], v2 = p[i2];
        float sum = fmaxf(v1 + v2, 1e-9f);
        g_tkidx[2 * t] = i1;  g_tkidx[2 * t + 1] = i2;
        g_tkw[2 * t] = v1 / sum;  g_tkw[2 * t + 1] = v2 / sum;
        g_argmax[t] = i1;
    }
}

// ---------------- deterministic per-expert compaction (1024 thr, 128 chunks)
#define NCH 128
__global__ void build_lists_kernel() {
    __shared__ int scnt[NCH][NEXP];
    __shared__ int choff[NCH][NEXP];
    __shared__ int eoff[NEXP];
    const int tid = threadIdx.x;
    const int e = tid & 7, ch = tid >> 3;
    const int t0 = ch * (TOKENS / NCH);
    int c = 0;
    for (int t = t0; t < t0 + TOKENS / NCH; t++) {
        if (g_tkidx[2 * t]     == e) c++;
        if (g_tkidx[2 * t + 1] == e) c++;
    }
    scnt[ch][e] = c;
    __syncthreads();
    if (tid < NEXP) {
        int s = 0;
        for (int j = 0; j < NCH; j++) { choff[j][tid] = s; s += scnt[j][tid]; }
        g_cnt[tid] = s;
    }
    __syncthreads();
    if (tid == 0) {
        int s = 0;
        for (int j = 0; j < NEXP; j++) { eoff[j] = s; g_off[j] = s; s += g_cnt[j]; }
        g_off[NEXP] = s;
    }
    __syncthreads();
    int pos = eoff[e] + choff[ch][e];
    for (int t = t0; t < t0 + TOKENS / NCH; t++) {
        #pragma unroll
        for (int k = 0; k < 2; k++)
            if (g_tkidx[2 * t + k] == e) {
                g_perm[pos] = t;
                g_wt[pos]   = g_tkw[2 * t + k];
                pos++;
            }
    }
}

// ---------------- aux loss ----------------
__global__ void aux_kernel(float* __restrict__ out, int out_size) {
    __shared__ float sp[NEXP][256];
    __shared__ int   sc[NEXP][256];
    const int tid = threadIdx.x;
    float p[NEXP]; int cc[NEXP];
    #pragma unroll
    for (int e = 0; e < NEXP; e++) { p[e] = 0.f; cc[e] = 0; }
    for (int t = tid; t < TOKENS; t += 256) {
        #pragma unroll
        for (int e = 0; e < NEXP; e++) p[e] += g_probs[t * NEXP + e];
        cc[g_argmax[t]]++;
    }
    #pragma unroll
    for (int e = 0; e < NEXP; e++) { sp[e][tid] = p[e]; sc[e][tid] = cc[e]; }
    __syncthreads();
    for (int s = 128; s > 0; s >>= 1) {
        if (tid < s) {
            #pragma unroll
            for (int e = 0; e < NEXP; e++) {
                sp[e][tid] += sp[e][tid + s];
                sc[e][tid] += sc[e][tid + s];
            }
        }
        __syncthreads();
    }
    if (tid == 0 && out_size > TOKENS * D_MODEL) {
        float aux = 0.f;
        #pragma unroll
        for (int e = 0; e < NEXP; e++)
            aux += ((float)sc[e][0] / (float)TOKENS) * (sp[e][0] / (float)TOKENS);
        out[out_size - 1] = (float)NEXP * aux;
    }
}

// ---------------- GEMM1 (128x128 tile): h = gelu(X_e @ W1[e] + b1) ----------
__global__ __launch_bounds__(256, 2)
void gemm1_mma(const __nv_bfloat16* __restrict__ xh,
               const __nv_bfloat16* __restrict__ xl,
               const __nv_bfloat16* __restrict__ W1h,
               const __nv_bfloat16* __restrict__ W1l,
               const float* __restrict__ b1,
               __nv_bfloat16* __restrict__ hh,
               __nv_bfloat16* __restrict__ hl) {
    const int e   = blockIdx.z;
    const int cnt = g_cnt[e];
    const int m0  = blockIdx.y * 128;
    if (m0 >= cnt) return;
    const int n0  = blockIdx.x * 128;
    const int off = g_off[e];

    extern __shared__ __align__(128) char smem[];
    const uint32_t sb = smem_u32(smem);
    const int tid = threadIdx.x;
    const int lid = tid & 31;
    const int wid = tid >> 5;
    const int wm = wid >> 1, wn = wid & 1;

    const int rA0 = tid >> 2;
    const int sA  = (tid & 3) * 16;
    const int rA1 = rA0 + 64;
    const int tok0 = (m0 + rA0 < cnt) ? g_perm[off + m0 + rA0] : g_perm[off];
    const int tok1 = (m0 + rA1 < cnt) ? g_perm[off + m0 + rA1] : g_perm[off];
    const __nv_bfloat16* a_h0 = xh + (size_t)tok0 * D_MODEL + (sA >> 1);
    const __nv_bfloat16* a_h1 = xh + (size_t)tok1 * D_MODEL + (sA >> 1);
    const __nv_bfloat16* a_l0 = xl + (size_t)tok0 * D_MODEL + (sA >> 1);
    const __nv_bfloat16* a_l1 = xl + (size_t)tok1 * D_MODEL + (sA >> 1);
    const uint32_t oA0 = (uint32_t)(AH_OFF + rA0 * 80 + sA);
    const uint32_t oA1 = (uint32_t)(AH_OFF + rA1 * 80 + sA);

    const int rB0 = tid >> 4;
    const int sB  = (tid & 15) * 16;
    const __nv_bfloat16* b_h = W1h + (size_t)e * D_MODEL * D_FF + (size_t)rB0 * D_FF + n0 + (sB >> 1);
    const __nv_bfloat16* b_l = W1l + (size_t)e * D_MODEL * D_FF + (size_t)rB0 * D_FF + n0 + (sB >> 1);
    const uint32_t oB0 = (uint32_t)(BH_OFF + rB0 * 272 + sB);
    const uint32_t oB1 = (uint32_t)(BH_OFF + (rB0 + 16) * 272 + sB);

    float acc[2][8][4];
    #pragma unroll
    for (int i = 0; i < 2; i++)
        #pragma unroll
        for (int j = 0; j < 8; j++)
            #pragma unroll
            for (int k = 0; k < 4; k++) acc[i][j][k] = 0.f;

    auto issue = [&](int c) {
        uint32_t st = sb + (uint32_t)((c % STAGES) * STAGE_BYTES);
        const int k0 = c * 32;
        cpa16(st + oA0, a_h0 + k0);
        cpa16(st + oA1, a_h1 + k0);
        cpa16(st + oA0 + (AL_OFF - AH_OFF), a_l0 + k0);
        cpa16(st + oA1 + (AL_OFF - AH_OFF), a_l1 + k0);
        const size_t bk = (size_t)k0 * D_FF;
        cpa16(st + oB0, b_h + bk);
        cpa16(st + oB1, b_h + bk + (size_t)16 * D_FF);
        cpa16(st + oB0 + (BL_OFF - BH_OFF), b_l + bk);
        cpa16(st + oB1 + (BL_OFF - BH_OFF), b_l + bk + (size_t)16 * D_FF);
        CP_COMMIT();
    };

    const int NC = D_MODEL / 32;   // 32
    issue(0); issue(1);
    for (int c = 0; c < NC; c++) {
        CP_WAIT1();
        __syncthreads();
        if (c + 2 < NC) issue(c + 2);
        compute_chunk(sb + (uint32_t)((c % STAGES) * STAGE_BYTES), wm, wn, lid, acc);
    }

    const int lgrp  = lid >> 2;
    const int lquad = (lid & 3) * 2;
    #pragma unroll
    for (int mi = 0; mi < 2; mi++) {
        const int r0 = m0 + wm * 32 + mi * 16 + lgrp;
        const int r1 = r0 + 8;
        #pragma unroll
        for (int n8 = 0; n8 < 8; n8++) {
            const int colg = n0 + wn * 64 + n8 * 8 + lquad;
            float2 bb = *(const float2*)(b1 + e * D_FF + colg);
            const float* a4 = acc[mi][n8];
            if (r0 < cnt) {
                float v0 = gelu_exact(a4[0] + bb.x);
                float v1 = gelu_exact(a4[1] + bb.y);
                __nv_bfloat16 h0 = __float2bfloat16_rn(v0);
                __nv_bfloat16 h1 = __float2bfloat16_rn(v1);
                size_t base = (size_t)(off + r0) * D_FF + colg;
                *(uint32_t*)(hh + base) = pack_bf2(h0, h1);
                *(uint32_t*)(hl + base) = pack_bf2(
                    __float2bfloat16_rn(v0 - __bfloat162float(h0)),
                    __float2bfloat16_rn(v1 - __bfloat162float(h1)));
            }
            if (r1 < cnt) {
                float v0 = gelu_exact(a4[2] + bb.x);
                float v1 = gelu_exact(a4[3] + bb.y);
                __nv_bfloat16 h0 = __float2bfloat16_rn(v0);
                __nv_bfloat16 h1 = __float2bfloat16_rn(v1);
                size_t base = (size_t)(off + r1) * D_FF + colg;
                *(uint32_t*)(hh + base) = pack_bf2(h0, h1);
                *(uint32_t*)(hl + base) = pack_bf2(
                    __float2bfloat16_rn(v0 - __bfloat162float(h0)),
                    __float2bfloat16_rn(v1 - __bfloat162float(h1)));
            }
        }
    }
}

// ---------------- GEMM2 (64x128 tile, 4-stage ring): out += w*(H@W2 + b2) ---
__global__ __launch_bounds__(256, 2)
void gemm2_mma(const __nv_bfloat16* __restrict__ hh,
               const __nv_bfloat16* __restrict__ hl,
               const __nv_bfloat16* __restrict__ W2h,
               const __nv_bfloat16* __restrict__ W2l,
               const float* __restrict__ b2,
               float* __restrict__ out) {
    const int e   = blockIdx.z;
    const int cnt = g_cnt[e];
    const int m0  = blockIdx.y * 64;
    if (m0 >= cnt) return;
    const int n0  = blockIdx.x * 128;
    const int off = g_off[e];

    extern __shared__ __align__(128) char smem[];
    const uint32_t sb = smem_u32(smem);
    const int tid = threadIdx.x;
    const int lid = tid & 31;
    const int wid = tid >> 5;
    const int wm = wid >> 2, wn = wid & 3;   // 2m x 4n warp grid

    const int rA = tid >> 2;             // 0..63
    const int sA = (tid & 3) * 16;
    const int rowA = (m0 + rA < cnt) ? (off + m0 + rA) : off;
    const __nv_bfloat16* a_h = hh + (size_t)rowA * D_FF + (sA >> 1);
    const __nv_bfloat16* a_l = hl + (size_t)rowA * D_FF + (sA >> 1);
    const uint32_t oA = (uint32_t)(rA * 80 + sA);

    const int rB0 = tid >> 4;
    const int sB  = (tid & 15) * 16;
    const __nv_bfloat16* b_h = W2h + (size_t)e * D_FF * D_MODEL + (size_t)rB0 * D_MODEL + n0 + (sB >> 1);
    const __nv_bfloat16* b_l = W2l + (size_t)e * D_FF * D_MODEL + (size_t)rB0 * D_MODEL + n0 + (sB >> 1);
    const uint32_t oB0 = (uint32_t)(B2H_OFF + rB0 * 272 + sB);
    const uint32_t oB1 = (uint32_t)(B2H_OFF + (rB0 + 16) * 272 + sB);

    float acc[2][4][4];
    #pragma unroll
    for (int i = 0; i < 2; i++)
        #pragma unroll
        for (int j = 0; j < 4; j++)
            #pragma unroll
            for (int k = 0; k < 4; k++) acc[i][j][k] = 0.f;

    auto issue = [&](int c) {
        uint32_t st = sb + (uint32_t)((c & (STAGES2 - 1)) * STAGE2_BYTES);
        const int k0 = c * 32;
        cpa16(st + oA, a_h + k0);
        cpa16(st + oA + A2L_DIFF, a_l + k0);
        const size_t bk = (size_t)k0 * D_MODEL;
        cpa16(st + oB0, b_h + bk);
        cpa16(st + oB1, b_h + bk + (size_t)16 * D_MODEL);
        cpa16(st + oB0 + B2L_DIFF, b_l + bk);
        cpa16(st + oB1 + B2L_DIFF, b_l + bk + (size_t)16 * D_MODEL);
        CP_COMMIT();
    };

    const int NC = D_FF / 32;   // 128
    issue(0); issue(1); issue(2);
    for (int c = 0; c < NC; c++) {
        CP_WAIT2();
        __syncthreads();
        if (c + 3 < NC) issue(c + 3);
        compute_chunk2(sb + (uint32_t)((c & (STAGES2 - 1)) * STAGE2_BYTES), wm, wn, lid, acc);
    }

    // epilogue: bias, gate-weight scale, vector atomic accumulate
    const int lgrp  = lid >> 2;
    const int lquad = (lid & 3) * 2;
    #pragma unroll
    for (int mi = 0; mi < 2; mi++) {
        const int r0 = m0 + wm * 32 + mi * 16 + lgrp;
        const int r1 = r0 + 8;
        const bool v0 = r0 < cnt, v1 = r1 < cnt;
        const int  s0 = v0 ? (off + r0) : off;
        const int  s1 = v1 ? (off + r1) : off;
        const int  t0 = g_perm[s0], t1 = g_perm[s1];
        const float w0 = v0 ? g_wt[s0] : 0.f;
        const float w1 = v1 ? g_wt[s1] : 0.f;
        #pragma unroll
        for (int n4 = 0; n4 < 4; n4++) {
            const int colg = n0 + wn * 32 + n4 * 8 + lquad;
            float2 bb = *(const float2*)(b2 + e * D_MODEL + colg);
            const float* a4 = acc[mi][n4];
            if (v0) {
                float2 v = make_float2(w0 * (a4[0] + bb.x), w0 * (a4[1] + bb.y));
                atomicAdd((float2*)(out + (size_t)t0 * D_MODEL + colg), v);
            }
            if (v1) {
                float2 v = make_float2(w1 * (a4[2] + bb.x), w1 * (a4[3] + bb.y));
                atomicAdd((float2*)(out + (size_t)t1 * D_MODEL + colg), v);
            }
        }
    }
}

// ---------------- launch: conv(W) || routing(+x-split), FULL join, GEMMs ----
extern "C" void kernel_launch(void* const* d_in, const int* in_sizes, int n_in,
                              void* d_out, int out_size) {
    const float* x  = (const float*)d_in[0];
    const float* Wr = (const float*)d_in[1];
    const float* br = (const float*)d_in[2];
    const float* W1 = (const float*)d_in[3];
    const float* b1 = (const float*)d_in[4];
    const float* W2 = (const float*)d_in[5];
    const float* b2 = (const float*)d_in[6];
    float* out = (float*)d_out;

    void *pW1h, *pW1l, *pW2h, *pW2l, *pxh, *pxl, *phh, *phl;
    cudaGetSymbolAddress(&pW1h, g_W1h);
    cudaGetSymbolAddress(&pW1l, g_W1l);
    cudaGetSymbolAddress(&pW2h, g_W2h);
    cudaGetSymbolAddress(&pW2l, g_W2l);
    cudaGetSymbolAddress(&pxh,  g_xh);
    cudaGetSymbolAddress(&pxl,  g_xl);
    cudaGetSymbolAddress(&phh,  g_hh);
    cudaGetSymbolAddress(&phl,  g_hl);

    cudaFuncSetAttribute(gemm1_mma, cudaFuncAttributeMaxDynamicSharedMemorySize, SMEM_BYTES);
    cudaFuncSetAttribute(gemm2_mma, cudaFuncAttributeMaxDynamicSharedMemorySize, SMEM2_BYTES);

    cudaStream_t s1;
    cudaEvent_t ev0, ev1;
    cudaStreamCreateWithFlags(&s1, cudaStreamNonBlocking);
    cudaEventCreateWithFlags(&ev0, cudaEventDisableTiming);
    cudaEventCreateWithFlags(&ev1, cudaEventDisableTiming);

    const int nW8 = NEXP * D_MODEL * D_FF / 8;   // 4194304 8-float groups

    // fork
    cudaEventRecord(ev0, 0);
    cudaStreamWaitEvent(s1, ev0, 0);

    // side stream: weight conv passes
    conv_split<<<nW8 / 1024, 256, 0, s1>>>(W1, (__nv_bfloat16*)pW1h, (__nv_bfloat16*)pW1l);
    conv_split<<<nW8 / 1024, 256, 0, s1>>>(W2, (__nv_bfloat16*)pW2h, (__nv_bfloat16*)pW2l);
    cudaEventRecord(ev1, s1);

    // main stream: routing chain (router also writes the x split)
    cudaMemsetAsync(out, 0, (size_t)TOKENS * D_MODEL * sizeof(float), 0);
    router_kernel<<<TOKENS, 128>>>(x, Wr, br, (__nv_bfloat16*)pxh, (__nv_bfloat16*)pxl);
    build_lists_kernel<<<1, 1024>>>();
    aux_kernel<<<1, 256>>>(out, out_size);

    // FULL join: GEMMs run with the GPU to themselves
    cudaStreamWaitEvent(0, ev1, 0);
    gemm1_mma<<<dim3(D_FF / 128, TOKENS / 128, NEXP), 256, SMEM_BYTES>>>(
        (const __nv_bfloat16*)pxh, (const __nv_bfloat16*)pxl,
        (const __nv_bfloat16*)pW1h, (const __nv_bfloat16*)pW1l, b1,
        (__nv_bfloat16*)phh, (__nv_bfloat16*)phl);
    gemm2_mma<<<dim3(D_MODEL / 128, TOKENS / 64, NEXP), 256, SMEM2_BYTES>>>(
        (const __nv_bfloat16*)phh, (const __nv_bfloat16*)phl,
        (const __nv_bfloat16*)pW2h, (const __nv_bfloat16*)pW2l, b2, out);
}